// round 7
// baseline (speedup 1.0000x reference)
#include <cuda_runtime.h>
#include <cuda_fp16.h>
#include <cstdint>

// Fused gather + 2-layer MLP, HMMA fp16, ldmatrix fragment loads.
//   x[67+pad] = [features16[lab] (64), centers[lab]-point (3)]
//   h = relu(x @ W1 + b1)   [128]
//   o = relu(h @ W2 + b2)   [64]
// fp16 inputs, fp32 accumulation; h chained register-resident between GEMMs.

#define TPB 256
#define TILES_PER_CTA 8
#define PTS_PER_CTA (TILES_PER_CTA * 128)
#define N_CLUSTERS 16384

#define XS  44             // X row stride in u32 (ldmatrix conflict-free)
#define W1S 44             // W1T row stride in u32
#define W2S 68             // W2T row stride in u32

// smem layout in u32 words
#define S_X   0                         // [128][44]
#define S_W1  (S_X + 128 * XS)          // [128][44]
#define S_W2  (S_W1 + 128 * W1S)        // [64][68]
#define S_B1  (S_W2 + 64 * W2S)         // 128 floats
#define S_B2  (S_B1 + 128)              // 64 floats
#define S_TOT (S_B2 + 64)
#define SMEM_BYTES (S_TOT * 4)          // 63232 B -> opt-in attribute required

// fp16 feature table: 16384 rows x 64 halfs = 128B/row (one cache line).
__device__ __align__(16) uint32_t g_feat16[N_CLUSTERS * 32];

__global__ void conv_feat_kernel(const float* __restrict__ features) {
    int i = blockIdx.x * blockDim.x + threadIdx.x;   // 0 .. 16384*32-1
    float2 v = ((const float2*)features)[i];
    __half2 h = __floats2half2_rn(v.x, v.y);
    g_feat16[i] = *reinterpret_cast<uint32_t*>(&h);
}

__device__ __forceinline__ void mma16816(float* d, const uint32_t* a,
                                         uint32_t b0, uint32_t b1) {
    asm volatile(
        "mma.sync.aligned.m16n8k16.row.col.f32.f16.f16.f32 "
        "{%0,%1,%2,%3}, {%4,%5,%6,%7}, {%8,%9}, {%0,%1,%2,%3};"
        : "+f"(d[0]), "+f"(d[1]), "+f"(d[2]), "+f"(d[3])
        : "r"(a[0]), "r"(a[1]), "r"(a[2]), "r"(a[3]), "r"(b0), "r"(b1));
}

__device__ __forceinline__ void ldsm_x4(uint32_t* r, uint32_t addr) {
    asm volatile("ldmatrix.sync.aligned.m8n8.x4.shared.b16 {%0,%1,%2,%3}, [%4];"
                 : "=r"(r[0]), "=r"(r[1]), "=r"(r[2]), "=r"(r[3]) : "r"(addr));
}
__device__ __forceinline__ void ldsm_x2(uint32_t* r, uint32_t addr) {
    asm volatile("ldmatrix.sync.aligned.m8n8.x2.shared.b16 {%0,%1}, [%2];"
                 : "=r"(r[0]), "=r"(r[1]) : "r"(addr));
}

__device__ __forceinline__ uint32_t pack2(float x, float y) {
    __half2 h = __floats2half2_rn(x, y);
    return *reinterpret_cast<uint32_t*>(&h);
}
__device__ __forceinline__ uint32_t rpack2(float x, float y) {
    return pack2(fmaxf(x, 0.0f), fmaxf(y, 0.0f));
}

__global__ __launch_bounds__(TPB, 2)
void fused_mlp_hmma_kernel(const int*   __restrict__ labels,
                           const float* __restrict__ centers,
                           const float* __restrict__ points,
                           const float* __restrict__ W1,
                           const float* __restrict__ b1,
                           const float* __restrict__ W2,
                           const float* __restrict__ b2,
                           float*       __restrict__ out,
                           int n)
{
    extern __shared__ uint32_t sm[];

    const int tid  = threadIdx.x;
    const int lane = tid & 31;
    const int warp = tid >> 5;
    const int gid  = lane >> 2;   // 0..7
    const int tig  = lane & 3;    // 0..3

    // ---------------- one-time per CTA: stage weights (fp16, transposed) ----
    for (int idx = tid; idx < 128 * W1S; idx += TPB) {
        int nn = idx / W1S;
        int ku = idx - nn * W1S;
        int k0 = 2 * ku;
        float v0 = (k0     < 67) ? W1[k0 * 128 + nn] : 0.0f;
        float v1 = (k0 + 1 < 67) ? W1[(k0 + 1) * 128 + nn] : 0.0f;
        sm[S_W1 + idx] = pack2(v0, v1);
    }
    for (int idx = tid; idx < 64 * W2S; idx += TPB) {
        int nn = idx / W2S;
        int ku = idx - nn * W2S;
        int k0 = 2 * ku;
        float v0 = (k0     < 128) ? W2[k0 * 64 + nn] : 0.0f;
        float v1 = (k0 + 1 < 128) ? W2[(k0 + 1) * 64 + nn] : 0.0f;
        sm[S_W2 + idx] = pack2(v0, v1);
    }
    if (tid < 128) ((float*)&sm[S_B1])[tid] = b1[tid];
    if (tid < 64)  ((float*)&sm[S_B2])[tid] = b2[tid];

    const int cta_base = blockIdx.x * PTS_PER_CTA;
    const int m0 = warp * 16;

    // ldmatrix per-lane base addresses (bytes, shared space)
    const uint32_t sbase = (uint32_t)__cvta_generic_to_shared(sm);
    const int l7  = lane & 7;
    const int g8  = (lane >> 3) & 1;
    const int g16 = (lane >> 4) & 1;
    // A: tiles {rows 0-7, rows 8-15} x {k-half 0, k-half 1}
    const uint32_t aAddr = sbase +
        4u * (S_X + (uint32_t)(m0 + l7 + g8 * 8) * XS + (uint32_t)g16 * 4);
    // B layer1: tiles {b0,b1} x {k-step s, s+1}
    const uint32_t b1Addr = sbase +
        4u * (S_W1 + (uint32_t)l7 * W1S + (uint32_t)g8 * 4 + (uint32_t)g16 * 8);
    // B layer1, lone k-step 4 (x2): {b0,b1}
    const uint32_t b1Addr4 = sbase +
        4u * (S_W1 + (uint32_t)l7 * W1S + 32 + (uint32_t)g8 * 4);
    // B layer2
    const uint32_t b2Addr = sbase +
        4u * (S_W2 + (uint32_t)l7 * W2S + (uint32_t)g8 * 4 + (uint32_t)g16 * 8);

    for (int t = 0; t < TILES_PER_CTA; t++) {
        const int tile_base = cta_base + t * 128;

        // ---- coalesced gather: 8 lanes per row; 1 LDG line + 1 STS.128 /pt ----
        {
            const int rr = lane >> 3;           // 0..3 (row within quad)
            const int c  = lane & 7;            // 16B chunk within row
            #pragma unroll
            for (int it = 0; it < 4; it++) {
                const int r   = warp * 16 + it * 4 + rr;
                const int lab = labels[tile_base + r];     // 8 lanes broadcast
                const uint4* src = (const uint4*)(g_feat16 + (size_t)lab * 32);
                uint4 d = __ldg(src + c);
                *(uint4*)&sm[S_X + r * XS + 4 * c] = d;
            }
        }
        // ---- coords: k=64..79 ------------------------------------------------
        {
            const int r = tid >> 1;
            if ((tid & 1) == 0) {
                const int p   = tile_base + r;
                const int lab = labels[p];
                float cx = centers[lab * 3 + 0] - points[(size_t)p * 3 + 0];
                float cy = centers[lab * 3 + 1] - points[(size_t)p * 3 + 1];
                float cz = centers[lab * 3 + 2] - points[(size_t)p * 3 + 2];
                uint32_t* xrow = &sm[S_X + r * XS];
                xrow[32] = pack2(cx, cy);
                xrow[33] = pack2(cz, 0.0f);
            } else {
                uint32_t* xrow = &sm[S_X + r * XS];
                #pragma unroll
                for (int u = 34; u < 40; u++) xrow[u] = 0u;   // pad k=68..79
            }
        }
        __syncthreads();

        // ---------------- layer 1: A fragments via ldmatrix ------------------
        uint32_t a[20];
        #pragma unroll
        for (int s = 0; s < 5; s++)
            ldsm_x4(&a[4 * s], aAddr + 32u * s);

        float acc1[64];
        #pragma unroll
        for (int i = 0; i < 64; i++) acc1[i] = 0.0f;

        #pragma unroll
        for (int j = 0; j < 16; j++) {          // 16 n-tiles of 8 hidden units
            const uint32_t bj = b1Addr + (uint32_t)j * (8 * W1S * 4);
            uint32_t b[4];
            ldsm_x4(b, bj);                      // b0,b1 for s=0 and s=1
            mma16816(&acc1[4 * j], &a[0], b[0], b[1]);
            mma16816(&acc1[4 * j], &a[4], b[2], b[3]);
            ldsm_x4(b, bj + 64);                 // s=2, s=3
            mma16816(&acc1[4 * j], &a[8],  b[0], b[1]);
            mma16816(&acc1[4 * j], &a[12], b[2], b[3]);
            ldsm_x2(b, b1Addr4 + (uint32_t)j * (8 * W1S * 4));   // s=4
            mma16816(&acc1[4 * j], &a[16], b[0], b[1]);
        }

        // -------- epilogue 1: relu(acc+b1) -> layer-2 A fragments (regs) ----
        uint32_t ha[32];
        {
            const float* sB1f = (const float*)&sm[S_B1];
            #pragma unroll
            for (int j2 = 0; j2 < 8; j2++) {
                const int nlo = 16 * j2 + 2 * tig;
                float2 bl = *(const float2*)&sB1f[nlo];
                float2 bh = *(const float2*)&sB1f[nlo + 8];
                const float* cl = &acc1[8 * j2];
                const float* ch = &acc1[8 * j2 + 4];
                ha[4 * j2 + 0] = rpack2(cl[0] + bl.x, cl[1] + bl.y);
                ha[4 * j2 + 1] = rpack2(cl[2] + bl.x, cl[3] + bl.y);
                ha[4 * j2 + 2] = rpack2(ch[0] + bh.x, ch[1] + bh.y);
                ha[4 * j2 + 3] = rpack2(ch[2] + bh.x, ch[3] + bh.y);
            }
        }

        // ---------------- layer 2: h (regs) x W2T ----------------------------
        float acc2[32];
        #pragma unroll
        for (int i = 0; i < 32; i++) acc2[i] = 0.0f;

        #pragma unroll
        for (int j = 0; j < 8; j++) {           // 8 n-tiles of 8 outputs
            const uint32_t bj = b2Addr + (uint32_t)j * (8 * W2S * 4);
            #pragma unroll
            for (int p = 0; p < 4; p++) {       // k-step pairs (2p, 2p+1)
                uint32_t b[4];
                ldsm_x4(b, bj + 64u * p);
                mma16816(&acc2[4 * j], &ha[8 * p],     b[0], b[1]);
                mma16816(&acc2[4 * j], &ha[8 * p + 4], b[2], b[3]);
            }
        }

        // ---------------- epilogue 2: relu + bias, direct stores ------------
        {
            const float* sB2f = (const float*)&sm[S_B2];
            float* o0 = out + (size_t)(tile_base + m0 + gid) * 64;
            float* o1 = o0 + 8 * 64;
            #pragma unroll
            for (int j = 0; j < 8; j++) {
                const int nn = 8 * j + 2 * tig;
                float2 bv = *(const float2*)&sB2f[nn];
                float2 v0, v1;
                v0.x = fmaxf(acc2[4 * j + 0] + bv.x, 0.0f);
                v0.y = fmaxf(acc2[4 * j + 1] + bv.y, 0.0f);
                v1.x = fmaxf(acc2[4 * j + 2] + bv.x, 0.0f);
                v1.y = fmaxf(acc2[4 * j + 3] + bv.y, 0.0f);
                *(float2*)(o0 + nn) = v0;
                *(float2*)(o1 + nn) = v1;
            }
        }
        __syncthreads();   // X reused by next tile's gather
    }
}

extern "C" void kernel_launch(void* const* d_in, const int* in_sizes, int n_in,
                              void* d_out, int out_size)
{
    const float* features = (const float*)d_in[0];
    const int*   labels   = (const int*)  d_in[1];
    const float* centers  = (const float*)d_in[2];
    const float* points   = (const float*)d_in[3];
    const float* W1       = (const float*)d_in[4];
    const float* b1       = (const float*)d_in[5];
    const float* W2       = (const float*)d_in[6];
    const float* b2       = (const float*)d_in[7];
    float* out = (float*)d_out;

    int n = in_sizes[1];                  // N_POINTS = 1048576

    // Prepass: fp32 features -> fp16 rows (128B each) in __device__ buffer.
    conv_feat_kernel<<<(N_CLUSTERS * 32) / 256, 256>>>(features);

    cudaFuncSetAttribute(fused_mlp_hmma_kernel,
                         cudaFuncAttributeMaxDynamicSharedMemorySize,
                         (int)SMEM_BYTES);

    int grid = n / PTS_PER_CTA;           // 1024
    fused_mlp_hmma_kernel<<<grid, TPB, SMEM_BYTES>>>(
        labels, centers, points, W1, b1, W2, b2, out, n);
}

// round 8
// speedup vs baseline: 1.2100x; 1.2100x over previous
#include <cuda_runtime.h>
#include <cuda_fp16.h>
#include <cstdint>

// Fused gather + 2-layer MLP, HMMA fp16, M=32/warp with interleaved layer-2.
//   x[67+pad] = [features16[lab] (64), centers[lab]-point (3)]
//   h = relu(x @ W1 + b1)   [128]   (never materialized: consumed 16 units
//   o = relu(h @ W2 + b2)   [64]     at a time as layer-2 k-steps)
// fp16 inputs, fp32 accumulation.

#define TPB 128
#define TILES_PER_CTA 8
#define PTS_PER_CTA (TILES_PER_CTA * 128)
#define N_CLUSTERS 16384

#define XS  44             // X row stride in u32 (ldmatrix conflict-free)
#define W1S 44             // W1T row stride in u32
#define W2S 68             // W2T row stride in u32

// smem layout in u32 words
#define S_X   0                         // [128][44]
#define S_W1  (S_X + 128 * XS)          // [128][44]
#define S_W2  (S_W1 + 128 * W1S)        // [64][68]
#define S_B1  (S_W2 + 64 * W2S)         // 128 floats
#define S_B2  (S_B1 + 128)              // 64 floats
#define S_TOT (S_B2 + 64)
#define SMEM_BYTES (S_TOT * 4)          // 63232 B

// fp16 feature table: 16384 rows x 64 halfs = 128B/row (one cache line).
__device__ __align__(16) uint32_t g_feat16[N_CLUSTERS * 32];

__global__ void conv_feat_kernel(const float* __restrict__ features) {
    int i = blockIdx.x * blockDim.x + threadIdx.x;   // 0 .. 16384*32-1
    float2 v = ((const float2*)features)[i];
    __half2 h = __floats2half2_rn(v.x, v.y);
    g_feat16[i] = *reinterpret_cast<uint32_t*>(&h);
}

__device__ __forceinline__ void mma16816(float* d, const uint32_t* a,
                                         uint32_t b0, uint32_t b1) {
    asm volatile(
        "mma.sync.aligned.m16n8k16.row.col.f32.f16.f16.f32 "
        "{%0,%1,%2,%3}, {%4,%5,%6,%7}, {%8,%9}, {%0,%1,%2,%3};"
        : "+f"(d[0]), "+f"(d[1]), "+f"(d[2]), "+f"(d[3])
        : "r"(a[0]), "r"(a[1]), "r"(a[2]), "r"(a[3]), "r"(b0), "r"(b1));
}

__device__ __forceinline__ void ldsm_x4(uint32_t* r, uint32_t addr) {
    asm volatile("ldmatrix.sync.aligned.m8n8.x4.shared.b16 {%0,%1,%2,%3}, [%4];"
                 : "=r"(r[0]), "=r"(r[1]), "=r"(r[2]), "=r"(r[3]) : "r"(addr));
}

__device__ __forceinline__ uint32_t pack2(float x, float y) {
    __half2 h = __floats2half2_rn(x, y);
    return *reinterpret_cast<uint32_t*>(&h);
}
__device__ __forceinline__ uint32_t rpack2(float x, float y) {
    return pack2(fmaxf(x, 0.0f), fmaxf(y, 0.0f));
}

__global__ __launch_bounds__(TPB, 3)
void fused_mlp_hmma_kernel(const int*   __restrict__ labels,
                           const float* __restrict__ centers,
                           const float* __restrict__ points,
                           const float* __restrict__ W1,
                           const float* __restrict__ b1,
                           const float* __restrict__ W2,
                           const float* __restrict__ b2,
                           float*       __restrict__ out,
                           int n)
{
    extern __shared__ uint32_t sm[];

    const int tid  = threadIdx.x;
    const int lane = tid & 31;
    const int warp = tid >> 5;    // 0..3
    const int gid  = lane >> 2;   // 0..7
    const int tig  = lane & 3;    // 0..3

    // ---------------- one-time per CTA: stage weights (fp16, transposed) ----
    for (int idx = tid; idx < 128 * W1S; idx += TPB) {
        int nn = idx / W1S;
        int ku = idx - nn * W1S;
        int k0 = 2 * ku;
        float v0 = (k0     < 67) ? W1[k0 * 128 + nn] : 0.0f;
        float v1 = (k0 + 1 < 67) ? W1[(k0 + 1) * 128 + nn] : 0.0f;
        sm[S_W1 + idx] = pack2(v0, v1);
    }
    for (int idx = tid; idx < 64 * W2S; idx += TPB) {
        int nn = idx / W2S;
        int ku = idx - nn * W2S;
        int k0 = 2 * ku;
        float v0 = (k0     < 128) ? W2[k0 * 64 + nn] : 0.0f;
        float v1 = (k0 + 1 < 128) ? W2[(k0 + 1) * 64 + nn] : 0.0f;
        sm[S_W2 + idx] = pack2(v0, v1);
    }
    ((float*)&sm[S_B1])[tid] = b1[tid];
    if (tid < 64) ((float*)&sm[S_B2])[tid] = b2[tid];

    const int cta_base = blockIdx.x * PTS_PER_CTA;
    const int m0 = warp * 32;     // 32 rows per warp (2 m-tiles)

    // ldmatrix per-lane base addresses (bytes, shared space)
    const uint32_t sbase = (uint32_t)__cvta_generic_to_shared(sm);
    const int l7  = lane & 7;
    const int g8  = (lane >> 3) & 1;
    const int g16 = (lane >> 4) & 1;
    // A (X): per m-tile: tiles {rows 0-7, rows 8-15} x {k-half 0, k-half 1}
    const uint32_t aAddr = sbase +
        4u * (S_X + (uint32_t)(m0 + l7 + g8 * 8) * XS + (uint32_t)g16 * 4);
    // B1 x4 per (jp, s): {b0,b1 of n-tile 2jp | b0,b1 of n-tile 2jp+1}
    const uint32_t b1Addr = sbase +
        4u * (S_W1 + (uint32_t)(l7 + g16 * 8) * W1S + (uint32_t)g8 * 4);
    // B2 x4 per (jj, jp): {b0,b1 of n-tile 2jj | b0,b1 of n-tile 2jj+1}
    const uint32_t b2Addr = sbase +
        4u * (S_W2 + (uint32_t)(l7 + g16 * 8) * W2S + (uint32_t)g8 * 4);

    for (int t = 0; t < TILES_PER_CTA; t++) {
        const int tile_base = cta_base + t * 128;

        // ---- coalesced gather: 8 lanes per row; 1 line LDG + 1 STS.128 /pt ----
        {
            const int rr = lane >> 3;           // 0..3
            const int c  = lane & 7;            // 16B chunk within row
            #pragma unroll
            for (int it = 0; it < 8; it++) {
                const int r   = warp * 32 + it * 4 + rr;
                const int lab = labels[tile_base + r];
                const uint4* src = (const uint4*)(g_feat16 + (size_t)lab * 32);
                uint4 d = __ldg(src + c);
                *(uint4*)&sm[S_X + r * XS + 4 * c] = d;
            }
        }
        // ---- coords + pad: 1 thread per row --------------------------------
        {
            const int r   = tid;
            const int p   = tile_base + r;
            const int lab = labels[p];
            float cx = centers[lab * 3 + 0] - points[(size_t)p * 3 + 0];
            float cy = centers[lab * 3 + 1] - points[(size_t)p * 3 + 1];
            float cz = centers[lab * 3 + 2] - points[(size_t)p * 3 + 2];
            uint32_t* xrow = &sm[S_X + r * XS];
            xrow[32] = pack2(cx, cy);
            xrow[33] = pack2(cz, 0.0f);
            #pragma unroll
            for (int u = 34; u < 40; u++) xrow[u] = 0u;
        }
        __syncthreads();

        // ---- A fragments for both m-tiles (reused by all 8 jp) -------------
        uint32_t a[40];   // [mt][s][4]
        #pragma unroll
        for (int mt = 0; mt < 2; mt++)
            #pragma unroll
            for (int s = 0; s < 5; s++)
                ldsm_x4(&a[mt * 20 + 4 * s],
                        aAddr + (uint32_t)mt * (16 * XS * 4) + 32u * s);

        float acc2[64];   // [mt][8 n-tiles][4]
        #pragma unroll
        for (int i = 0; i < 64; i++) acc2[i] = 0.0f;

        const float* sB1f = (const float*)&sm[S_B1];

        // ============ interleaved mainloop: 16 hidden units per jp ==========
        #pragma unroll
        for (int jp = 0; jp < 8; jp++) {
            // B1 fragments for n-tiles {2jp, 2jp+1}, all 5 k-steps
            uint32_t b[20];   // [s][4] = {b0,b1 | b0',b1'}
            #pragma unroll
            for (int s = 0; s < 5; s++)
                ldsm_x4(&b[4 * s],
                        b1Addr + (uint32_t)jp * (16 * W1S * 4) + 32u * s);

            // layer-1 partial: 2 m-tiles x 2 n-tiles x 5 k
            float acc1[16];
            #pragma unroll
            for (int i = 0; i < 16; i++) acc1[i] = 0.0f;
            #pragma unroll
            for (int mt = 0; mt < 2; mt++)
                #pragma unroll
                for (int s = 0; s < 5; s++) {
                    mma16816(&acc1[mt * 8],     &a[mt * 20 + 4 * s], b[4 * s],     b[4 * s + 1]);
                    mma16816(&acc1[mt * 8 + 4], &a[mt * 20 + 4 * s], b[4 * s + 2], b[4 * s + 3]);
                }

            // epilogue-1: relu+bias -> layer-2 A fragment (k-step jp)
            const int nlo = 16 * jp + 2 * tig;
            float2 bl = *(const float2*)&sB1f[nlo];
            float2 bh = *(const float2*)&sB1f[nlo + 8];
            uint32_t ha[8];   // [mt][4]
            #pragma unroll
            for (int mt = 0; mt < 2; mt++) {
                const float* cl = &acc1[mt * 8];
                const float* ch = &acc1[mt * 8 + 4];
                ha[mt * 4 + 0] = rpack2(cl[0] + bl.x, cl[1] + bl.y);
                ha[mt * 4 + 1] = rpack2(cl[2] + bl.x, cl[3] + bl.y);
                ha[mt * 4 + 2] = rpack2(ch[0] + bh.x, ch[1] + bh.y);
                ha[mt * 4 + 3] = rpack2(ch[2] + bh.x, ch[3] + bh.y);
            }

            // layer-2 partial: k-step jp against all 8 n-tiles
            #pragma unroll
            for (int jj = 0; jj < 4; jj++) {
                uint32_t bb[4];
                ldsm_x4(bb, b2Addr + (uint32_t)jj * (16 * W2S * 4) + 32u * jp);
                #pragma unroll
                for (int mt = 0; mt < 2; mt++) {
                    mma16816(&acc2[mt * 32 + 8 * jj],     &ha[mt * 4], bb[0], bb[1]);
                    mma16816(&acc2[mt * 32 + 8 * jj + 4], &ha[mt * 4], bb[2], bb[3]);
                }
            }
        }

        // ---------------- epilogue 2: relu + bias, direct stores ------------
        {
            const float* sB2f = (const float*)&sm[S_B2];
            #pragma unroll
            for (int mt = 0; mt < 2; mt++) {
                float* o0 = out + (size_t)(tile_base + m0 + 16 * mt + gid) * 64;
                float* o1 = o0 + 8 * 64;
                #pragma unroll
                for (int j = 0; j < 8; j++) {
                    const int nn = 8 * j + 2 * tig;
                    float2 bv = *(const float2*)&sB2f[nn];
                    const float* c = &acc2[mt * 32 + 4 * j];
                    float2 v0, v1;
                    v0.x = fmaxf(c[0] + bv.x, 0.0f);
                    v0.y = fmaxf(c[1] + bv.y, 0.0f);
                    v1.x = fmaxf(c[2] + bv.x, 0.0f);
                    v1.y = fmaxf(c[3] + bv.y, 0.0f);
                    *(float2*)(o0 + nn) = v0;
                    *(float2*)(o1 + nn) = v1;
                }
            }
        }
        __syncthreads();   // X reused by next tile's gather
    }
}

extern "C" void kernel_launch(void* const* d_in, const int* in_sizes, int n_in,
                              void* d_out, int out_size)
{
    const float* features = (const float*)d_in[0];
    const int*   labels   = (const int*)  d_in[1];
    const float* centers  = (const float*)d_in[2];
    const float* points   = (const float*)d_in[3];
    const float* W1       = (const float*)d_in[4];
    const float* b1       = (const float*)d_in[5];
    const float* W2       = (const float*)d_in[6];
    const float* b2       = (const float*)d_in[7];
    float* out = (float*)d_out;

    int n = in_sizes[1];                  // N_POINTS = 1048576

    conv_feat_kernel<<<(N_CLUSTERS * 32) / 256, 256>>>(features);

    cudaFuncSetAttribute(fused_mlp_hmma_kernel,
                         cudaFuncAttributeMaxDynamicSharedMemorySize,
                         (int)SMEM_BYTES);

    int grid = n / PTS_PER_CTA;           // 1024
    fused_mlp_hmma_kernel<<<grid, TPB, SMEM_BYTES>>>(
        labels, centers, points, W1, b1, W2, b2, out, n);
}

// round 9
// speedup vs baseline: 1.2496x; 1.0328x over previous
#include <cuda_runtime.h>
#include <cuda_fp16.h>
#include <cstdint>

// Fused gather + 2-layer MLP, HMMA fp16, M=32/warp, interleaved layer-2,
// per-warp software-pipelined gather (cp.async, no CTA barriers in the loop).
//   x[67+pad] = [features16[lab] (64), centers[lab]-point (3)]
//   h = relu(x @ W1 + b1)   [128]  (consumed 16 units/jp as layer-2 k-steps)
//   o = relu(h @ W2 + b2)   [64]

#define TPB 128
#define TILES_PER_CTA 8
#define PTS_PER_CTA (TILES_PER_CTA * 128)
#define N_CLUSTERS 16384

#define XS  44             // X row stride in u32 (ldmatrix conflict-free)
#define W1S 44             // W1T row stride in u32
#define W2S 68             // W2T row stride in u32

// smem layout in u32 words
#define S_X   0                         // [128][44]  (per-warp 32-row slices)
#define S_W1  (S_X + 128 * XS)          // [128][44]
#define S_W2  (S_W1 + 128 * W1S)        // [64][68]
#define S_B1  (S_W2 + 64 * W2S)         // 128 floats
#define S_B2  (S_B1 + 128)              // 64 floats
#define S_TOT (S_B2 + 64)
#define SMEM_BYTES (S_TOT * 4)          // 63232 B

// fp16 feature table: 16384 rows x 64 halfs = 128B/row (one cache line).
__device__ __align__(16) uint32_t g_feat16[N_CLUSTERS * 32];

__global__ void conv_feat_kernel(const float* __restrict__ features) {
    int i = blockIdx.x * blockDim.x + threadIdx.x;   // 0 .. 16384*32-1
    float2 v = ((const float2*)features)[i];
    __half2 h = __floats2half2_rn(v.x, v.y);
    g_feat16[i] = *reinterpret_cast<uint32_t*>(&h);
}

__device__ __forceinline__ void mma16816(float* d, const uint32_t* a,
                                         uint32_t b0, uint32_t b1) {
    asm volatile(
        "mma.sync.aligned.m16n8k16.row.col.f32.f16.f16.f32 "
        "{%0,%1,%2,%3}, {%4,%5,%6,%7}, {%8,%9}, {%0,%1,%2,%3};"
        : "+f"(d[0]), "+f"(d[1]), "+f"(d[2]), "+f"(d[3])
        : "r"(a[0]), "r"(a[1]), "r"(a[2]), "r"(a[3]), "r"(b0), "r"(b1));
}

__device__ __forceinline__ void ldsm_x4(uint32_t* r, uint32_t addr) {
    asm volatile("ldmatrix.sync.aligned.m8n8.x4.shared.b16 {%0,%1,%2,%3}, [%4];"
                 : "=r"(r[0]), "=r"(r[1]), "=r"(r[2]), "=r"(r[3]) : "r"(addr));
}

__device__ __forceinline__ void cp_async16(uint32_t saddr, const void* gaddr) {
    asm volatile("cp.async.cg.shared.global [%0], [%1], 16;"
                 :: "r"(saddr), "l"(gaddr));
}
#define CP_COMMIT() asm volatile("cp.async.commit_group;" ::: "memory")
#define CP_WAIT0()  asm volatile("cp.async.wait_group 0;" ::: "memory")

__device__ __forceinline__ uint32_t pack2(float x, float y) {
    __half2 h = __floats2half2_rn(x, y);
    return *reinterpret_cast<uint32_t*>(&h);
}
__device__ __forceinline__ uint32_t rpack2(float x, float y) {
    return pack2(fmaxf(x, 0.0f), fmaxf(y, 0.0f));
}

__global__ __launch_bounds__(TPB, 3)
void fused_mlp_hmma_kernel(const int*   __restrict__ labels,
                           const float* __restrict__ centers,
                           const float* __restrict__ points,
                           const float* __restrict__ W1,
                           const float* __restrict__ b1,
                           const float* __restrict__ W2,
                           const float* __restrict__ b2,
                           float*       __restrict__ out,
                           int n)
{
    extern __shared__ uint32_t sm[];

    const int tid  = threadIdx.x;
    const int lane = tid & 31;
    const int warp = tid >> 5;    // 0..3
    const int gid  = lane >> 2;   // 0..7
    const int tig  = lane & 3;    // 0..3

    // ---------------- one-time per CTA: stage weights (fp16, transposed) ----
    for (int idx = tid; idx < 128 * W1S; idx += TPB) {
        int nn = idx / W1S;
        int ku = idx - nn * W1S;
        int k0 = 2 * ku;
        float v0 = (k0     < 67) ? W1[k0 * 128 + nn] : 0.0f;
        float v1 = (k0 + 1 < 67) ? W1[(k0 + 1) * 128 + nn] : 0.0f;
        sm[S_W1 + idx] = pack2(v0, v1);
    }
    for (int idx = tid; idx < 64 * W2S; idx += TPB) {
        int nn = idx / W2S;
        int ku = idx - nn * W2S;
        int k0 = 2 * ku;
        float v0 = (k0     < 128) ? W2[k0 * 64 + nn] : 0.0f;
        float v1 = (k0 + 1 < 128) ? W2[(k0 + 1) * 64 + nn] : 0.0f;
        sm[S_W2 + idx] = pack2(v0, v1);
    }
    ((float*)&sm[S_B1])[tid] = b1[tid];
    if (tid < 64) ((float*)&sm[S_B2])[tid] = b2[tid];
    __syncthreads();   // weights visible to all warps; the ONLY CTA barrier

    const int cta_base = blockIdx.x * PTS_PER_CTA;
    const int m0 = warp * 32;     // this warp's 32 private rows

    // ldmatrix / cp.async per-lane base addresses (bytes, shared space)
    const uint32_t sbase = (uint32_t)__cvta_generic_to_shared(sm);
    const int l7  = lane & 7;
    const int g8  = (lane >> 3) & 1;
    const int g16 = (lane >> 4) & 1;
    const uint32_t aAddr = sbase +
        4u * (S_X + (uint32_t)(m0 + l7 + g8 * 8) * XS + (uint32_t)g16 * 4);
    const uint32_t b1Addr = sbase +
        4u * (S_W1 + (uint32_t)(l7 + g16 * 8) * W1S + (uint32_t)g8 * 4);
    const uint32_t b2Addr = sbase +
        4u * (S_W2 + (uint32_t)(l7 + g16 * 8) * W2S + (uint32_t)g8 * 4);

    // gather lane roles
    const int rr = lane >> 3;            // 0..3 (row within quad)
    const int cc = lane & 7;             // 16B chunk within feature row

    // ---- per-warp gather of tile t's 32 rows (async features + coords) ----
    auto gather_tile = [&](int t) {
        const int tile_base = cta_base + t * 128;
        #pragma unroll
        for (int it = 0; it < 8; it++) {
            const int r   = m0 + it * 4 + rr;
            const int lab = labels[tile_base + r];
            cp_async16(sbase + 4u * (S_X + (uint32_t)r * XS + 4u * cc),
                       (const char*)(g_feat16 + (size_t)lab * 32) + 16 * cc);
        }
        CP_COMMIT();
        // coords + pad: one row per lane (regular LDG + STS)
        const int r   = m0 + lane;
        const int p   = tile_base + r;
        const int lab = labels[p];
        float cx = centers[lab * 3 + 0] - points[(size_t)p * 3 + 0];
        float cy = centers[lab * 3 + 1] - points[(size_t)p * 3 + 1];
        float cz = centers[lab * 3 + 2] - points[(size_t)p * 3 + 2];
        uint32_t* xrow = &sm[S_X + r * XS];
        xrow[32] = pack2(cx, cy);
        xrow[33] = pack2(cz, 0.0f);
        #pragma unroll
        for (int u = 34; u < 40; u++) xrow[u] = 0u;
    };

    // prologue: gather tile 0
    gather_tile(0);
    CP_WAIT0();
    __syncwarp();

    for (int t = 0; t < TILES_PER_CTA; t++) {
        const int tile_base = cta_base + t * 128;

        // ---- A fragments for both m-tiles (consumes this warp's X slice) ---
        uint32_t a[40];   // [mt][s][4]
        #pragma unroll
        for (int mt = 0; mt < 2; mt++)
            #pragma unroll
            for (int s = 0; s < 5; s++)
                ldsm_x4(&a[mt * 20 + 4 * s],
                        aAddr + (uint32_t)mt * (16 * XS * 4) + 32u * s);

        // X slice now dead -> prefetch next tile's gather behind the mainloop
        if (t + 1 < TILES_PER_CTA) gather_tile(t + 1);

        float acc2[64];   // [mt][8 n-tiles][4]
        #pragma unroll
        for (int i = 0; i < 64; i++) acc2[i] = 0.0f;

        const float* sB1f = (const float*)&sm[S_B1];

        // ============ interleaved mainloop: 16 hidden units per jp ==========
        #pragma unroll
        for (int jp = 0; jp < 8; jp++) {
            uint32_t b[20];   // B1 frags: n-tiles {2jp,2jp+1}, 5 k-steps
            #pragma unroll
            for (int s = 0; s < 5; s++)
                ldsm_x4(&b[4 * s],
                        b1Addr + (uint32_t)jp * (16 * W1S * 4) + 32u * s);

            float acc1[16];
            #pragma unroll
            for (int i = 0; i < 16; i++) acc1[i] = 0.0f;
            #pragma unroll
            for (int mt = 0; mt < 2; mt++)
                #pragma unroll
                for (int s = 0; s < 5; s++) {
                    mma16816(&acc1[mt * 8],     &a[mt * 20 + 4 * s], b[4 * s],     b[4 * s + 1]);
                    mma16816(&acc1[mt * 8 + 4], &a[mt * 20 + 4 * s], b[4 * s + 2], b[4 * s + 3]);
                }

            // epilogue-1: relu+bias -> layer-2 A fragment (k-step jp)
            const int nlo = 16 * jp + 2 * tig;
            float2 bl = *(const float2*)&sB1f[nlo];
            float2 bh = *(const float2*)&sB1f[nlo + 8];
            uint32_t ha[8];
            #pragma unroll
            for (int mt = 0; mt < 2; mt++) {
                const float* cl = &acc1[mt * 8];
                const float* ch = &acc1[mt * 8 + 4];
                ha[mt * 4 + 0] = rpack2(cl[0] + bl.x, cl[1] + bl.y);
                ha[mt * 4 + 1] = rpack2(cl[2] + bl.x, cl[3] + bl.y);
                ha[mt * 4 + 2] = rpack2(ch[0] + bh.x, ch[1] + bh.y);
                ha[mt * 4 + 3] = rpack2(ch[2] + bh.x, ch[3] + bh.y);
            }

            // layer-2 partial: k-step jp against all 8 n-tiles
            #pragma unroll
            for (int jj = 0; jj < 4; jj++) {
                uint32_t bb[4];
                ldsm_x4(bb, b2Addr + (uint32_t)jj * (16 * W2S * 4) + 32u * jp);
                #pragma unroll
                for (int mt = 0; mt < 2; mt++) {
                    mma16816(&acc2[mt * 32 + 8 * jj],     &ha[mt * 4], bb[0], bb[1]);
                    mma16816(&acc2[mt * 32 + 8 * jj + 4], &ha[mt * 4], bb[2], bb[3]);
                }
            }
        }

        // ---------------- epilogue 2: relu + bias, direct stores ------------
        {
            const float* sB2f = (const float*)&sm[S_B2];
            #pragma unroll
            for (int mt = 0; mt < 2; mt++) {
                float* o0 = out + (size_t)(tile_base + m0 + 16 * mt + gid) * 64;
                float* o1 = o0 + 8 * 64;
                #pragma unroll
                for (int j = 0; j < 8; j++) {
                    const int nn = 8 * j + 2 * tig;
                    float2 bv = *(const float2*)&sB2f[nn];
                    const float* c = &acc2[mt * 32 + 4 * j];
                    float2 v0, v1;
                    v0.x = fmaxf(c[0] + bv.x, 0.0f);
                    v0.y = fmaxf(c[1] + bv.y, 0.0f);
                    v1.x = fmaxf(c[2] + bv.x, 0.0f);
                    v1.y = fmaxf(c[3] + bv.y, 0.0f);
                    *(float2*)(o0 + nn) = v0;
                    *(float2*)(o1 + nn) = v1;
                }
            }
        }

        // next tile's async features must have landed before its ldsm reads
        if (t + 1 < TILES_PER_CTA) {
            CP_WAIT0();
            __syncwarp();
        }
    }
}

extern "C" void kernel_launch(void* const* d_in, const int* in_sizes, int n_in,
                              void* d_out, int out_size)
{
    const float* features = (const float*)d_in[0];
    const int*   labels   = (const int*)  d_in[1];
    const float* centers  = (const float*)d_in[2];
    const float* points   = (const float*)d_in[3];
    const float* W1       = (const float*)d_in[4];
    const float* b1       = (const float*)d_in[5];
    const float* W2       = (const float*)d_in[6];
    const float* b2       = (const float*)d_in[7];
    float* out = (float*)d_out;

    int n = in_sizes[1];                  // N_POINTS = 1048576

    conv_feat_kernel<<<(N_CLUSTERS * 32) / 256, 256>>>(features);

    cudaFuncSetAttribute(fused_mlp_hmma_kernel,
                         cudaFuncAttributeMaxDynamicSharedMemorySize,
                         (int)SMEM_BYTES);

    int grid = n / PTS_PER_CTA;           // 1024
    fused_mlp_hmma_kernel<<<grid, TPB, SMEM_BYTES>>>(
        labels, centers, points, W1, b1, W2, b2, out, n);
}